// round 1
// baseline (speedup 1.0000x reference)
#include <cuda_runtime.h>
#include <math.h>

#define BB 2
#define SS 2048
#define EE 1024
#define HH 16
#define DKK 64
#define MM (BB*SS)        // 4096 rows of x
#define BHS (BB*HH*SS)    // 65536

// Scratch (static device globals — no runtime allocation).
// Layout: [B, H, S, DK] contiguous in DK.
__device__ float g_k[BHS * DKK];
__device__ float g_v[BHS * DKK];
__device__ float g_q[BHS * DKK];

// ---------------------------------------------------------------------------
// Projection GEMM: C[m,n] = sum_e A[m,e] * W[n,e]   (A: [4096,1024], W: [1024,1024])
// Output scattered to [B,H,S,DK]:  m = b*S+s,  n = h*DK+d
// mode 0/1: plain write (K, V).  mode 2: cos(val + theta[d]) * 0.125 (Q, pre-scaled by 1/sqrt(dk))
// Block tile 64x64, 256 threads, 4x4 register micro-tile, K-chunks of 16.
// ---------------------------------------------------------------------------
__global__ __launch_bounds__(256)
void proj_kernel(const float* __restrict__ A,
                 const float* __restrict__ W,
                 const float* __restrict__ theta,
                 float* __restrict__ dst,
                 int mode)
{
    __shared__ float As[16][64];
    __shared__ float Ws[16][64];

    const int tid  = threadIdx.x;
    const int tx   = tid & 15;
    const int ty   = tid >> 4;
    const int row0 = blockIdx.y * 64;
    const int col0 = blockIdx.x * 64;

    const int lr = tid >> 2;        // 0..63  (tile row to load)
    const int lk = (tid & 3) * 4;   // 0,4,8,12 (k offset, float4)

    float acc[4][4];
    #pragma unroll
    for (int i = 0; i < 4; i++)
        #pragma unroll
        for (int j = 0; j < 4; j++) acc[i][j] = 0.f;

    for (int k0 = 0; k0 < EE; k0 += 16) {
        float4 av = *(const float4*)&A[(row0 + lr) * EE + k0 + lk];
        float4 wv = *(const float4*)&W[(col0 + lr) * EE + k0 + lk];
        As[lk + 0][lr] = av.x; As[lk + 1][lr] = av.y;
        As[lk + 2][lr] = av.z; As[lk + 3][lr] = av.w;
        Ws[lk + 0][lr] = wv.x; Ws[lk + 1][lr] = wv.y;
        Ws[lk + 2][lr] = wv.z; Ws[lk + 3][lr] = wv.w;
        __syncthreads();

        #pragma unroll
        for (int kk = 0; kk < 16; kk++) {
            float4 a4 = *(const float4*)&As[kk][ty * 4];
            float4 w4 = *(const float4*)&Ws[kk][tx * 4];
            float a[4] = {a4.x, a4.y, a4.z, a4.w};
            float w[4] = {w4.x, w4.y, w4.z, w4.w};
            #pragma unroll
            for (int i = 0; i < 4; i++)
                #pragma unroll
                for (int j = 0; j < 4; j++)
                    acc[i][j] = fmaf(a[i], w[j], acc[i][j]);
        }
        __syncthreads();
    }

    #pragma unroll
    for (int i = 0; i < 4; i++) {
        int m = row0 + ty * 4 + i;
        int b = m >> 11;            // m / S
        int s = m & (SS - 1);
        #pragma unroll
        for (int j = 0; j < 4; j++) {
            int n = col0 + tx * 4 + j;
            int h = n >> 6;         // n / DK
            int d = n & (DKK - 1);
            float v = acc[i][j];
            if (mode == 2) v = cosf(v + theta[d]) * 0.125f;  // 1/sqrt(64) folded in
            dst[(((b * HH + h) * SS) + s) * DKK + d] = v;
        }
    }
}

// ---------------------------------------------------------------------------
// Flash attention: one thread per query row. grid = (S/128, B*H), block = 128.
// q[64] and acc[64] in registers; 64-key K/V tiles staged in smem.
// Online softmax with lazy rescale (rescale only when running max increases).
// ---------------------------------------------------------------------------
__global__ __launch_bounds__(128)
void attn_kernel(float* __restrict__ out)
{
    __shared__ float Ks[64][64];
    __shared__ float Vs[64][64];

    const int bh = blockIdx.y;          // 0..31
    const int b  = bh >> 4;
    const int h  = bh & (HH - 1);
    const int qi = blockIdx.x * 128 + threadIdx.x;

    const float* qrow = &g_q[((size_t)bh * SS + qi) * DKK];
    float q[DKK];
    #pragma unroll
    for (int d = 0; d < DKK; d++) q[d] = qrow[d];

    float mx = -1e30f;
    float l  = 0.f;
    float acc[DKK];
    #pragma unroll
    for (int d = 0; d < DKK; d++) acc[d] = 0.f;

    const float4* kbase = (const float4*)&g_k[(size_t)bh * SS * DKK];
    const float4* vbase = (const float4*)&g_v[(size_t)bh * SS * DKK];

    for (int t0 = 0; t0 < SS; t0 += 64) {
        // Stage 64x64 K and V tiles (1024 float4 each, coalesced).
        const float4* ksrc = kbase + (size_t)t0 * 16;   // t0*DK/4
        const float4* vsrc = vbase + (size_t)t0 * 16;
        float4* kdst = (float4*)&Ks[0][0];
        float4* vdst = (float4*)&Vs[0][0];
        #pragma unroll
        for (int f = threadIdx.x; f < 1024; f += 128) {
            kdst[f] = ksrc[f];
            vdst[f] = vsrc[f];
        }
        __syncthreads();

        #pragma unroll 1
        for (int j = 0; j < 64; j++) {
            // score = q . K[j]   (q already carries 1/sqrt(dk))
            const float4* kr = (const float4*)&Ks[j][0];
            float s0 = 0.f, s1 = 0.f, s2 = 0.f, s3 = 0.f;
            #pragma unroll
            for (int d4 = 0; d4 < 16; d4++) {
                float4 kv = kr[d4];
                s0 = fmaf(q[4 * d4 + 0], kv.x, s0);
                s1 = fmaf(q[4 * d4 + 1], kv.y, s1);
                s2 = fmaf(q[4 * d4 + 2], kv.z, s2);
                s3 = fmaf(q[4 * d4 + 3], kv.w, s3);
            }
            float sc = (s0 + s1) + (s2 + s3);

            if (sc > mx) {                      // rare after warm-up
                float corr = __expf(mx - sc);
                l *= corr;
                #pragma unroll
                for (int d = 0; d < DKK; d++) acc[d] *= corr;
                mx = sc;
            }
            float p = __expf(sc - mx);
            l += p;

            const float4* vr = (const float4*)&Vs[j][0];
            #pragma unroll
            for (int d4 = 0; d4 < 16; d4++) {
                float4 vv = vr[d4];
                acc[4 * d4 + 0] = fmaf(p, vv.x, acc[4 * d4 + 0]);
                acc[4 * d4 + 1] = fmaf(p, vv.y, acc[4 * d4 + 1]);
                acc[4 * d4 + 2] = fmaf(p, vv.z, acc[4 * d4 + 2]);
                acc[4 * d4 + 3] = fmaf(p, vv.w, acc[4 * d4 + 3]);
            }
        }
        __syncthreads();
    }

    float inv = 1.f / l;
    float* o = &out[(((size_t)b * SS + qi) * EE) + h * DKK];
    #pragma unroll
    for (int d = 0; d < DKK; d++) o[d] = acc[d] * inv;
}

// ---------------------------------------------------------------------------
// Launch. Inputs (metadata order): x, Wk, Wv, Wq, theta. Output: float [B,S,E].
// ---------------------------------------------------------------------------
extern "C" void kernel_launch(void* const* d_in, const int* in_sizes, int n_in,
                              void* d_out, int out_size)
{
    const float* x     = (const float*)d_in[0];
    const float* Wk    = (const float*)d_in[1];
    const float* Wv    = (const float*)d_in[2];
    const float* Wq    = (const float*)d_in[3];
    const float* theta = (const float*)d_in[4];
    float* out = (float*)d_out;

    float *gk, *gv, *gq;
    cudaGetSymbolAddress((void**)&gk, g_k);
    cudaGetSymbolAddress((void**)&gv, g_v);
    cudaGetSymbolAddress((void**)&gq, g_q);

    dim3 gg(EE / 64, MM / 64);   // (16, 64)
    proj_kernel<<<gg, 256>>>(x, Wk, theta, gk, 0);
    proj_kernel<<<gg, 256>>>(x, Wv, theta, gv, 1);
    proj_kernel<<<gg, 256>>>(x, Wq, theta, gq, 2);

    dim3 ga(SS / 128, BB * HH);  // (16, 32)
    attn_kernel<<<ga, 128>>>(out);
}

// round 3
// speedup vs baseline: 4.2196x; 4.2196x over previous
#include <cuda_runtime.h>
#include <math.h>
#include <stdint.h>

#define BBATCH 2
#define SSEQ 2048
#define EEMB 1024
#define HHEADS 16
#define DKK 64
#define BHS (BBATCH*HHEADS*SSEQ)

// Scratch: K, V as [bh][s][d], Q as [bh][s][d]
__device__ float g_k[BHS*DKK];
__device__ float g_v[BHS*DKK];
__device__ float g_q[BHS*DKK];

// ---------------- helpers ----------------
__device__ __forceinline__ float to_tf32(float x){
    float r; asm("cvt.rna.tf32.f32 %0, %1;" : "=f"(r) : "f"(x)); return r;
}
__device__ __forceinline__ void rnd4(float4& v){
    v.x = to_tf32(v.x); v.y = to_tf32(v.y); v.z = to_tf32(v.z); v.w = to_tf32(v.w);
}
// mma.sync m16n8k8 tf32: D = A*B + C (row.col), fp32 accum
__device__ __forceinline__ void mma8(float* d,
                                     const uint32_t a0, const uint32_t a1,
                                     const uint32_t a2, const uint32_t a3,
                                     const uint32_t b0, const uint32_t b1)
{
    asm volatile("mma.sync.aligned.m16n8k8.row.col.f32.tf32.tf32.f32 "
        "{%0,%1,%2,%3}, {%4,%5,%6,%7}, {%8,%9}, {%0,%1,%2,%3};"
        : "+f"(d[0]), "+f"(d[1]), "+f"(d[2]), "+f"(d[3])
        : "r"(a0), "r"(a1), "r"(a2), "r"(a3), "r"(b0), "r"(b1));
}

// =====================================================================
// Projection GEMM: C[m,n] = sum_e A[m,e]*W[n,e]. M=4096, N=1024, K=1024.
// CTA 128x128, 256 threads, 8 warps (4x2), warp tile 32x64, BK=32.
// mode 0: K, mode 1: V, mode 2: Q=cos(v+theta)*0.125. All -> [bh][s][d].
// =====================================================================
#define PPAD 36

__global__ __launch_bounds__(256)
void proj_mma(const float* __restrict__ A, const float* __restrict__ W,
              const float* __restrict__ theta, float* __restrict__ dst, int mode)
{
    __shared__ float As[128][PPAD];
    __shared__ float Bs[128][PPAD];

    const int tid  = threadIdx.x;
    const int wid  = tid >> 5, lane = tid & 31;
    const int gid  = lane >> 2, tig = lane & 3;
    const int wm   = wid >> 1, wn = wid & 1;
    const int row0 = blockIdx.y * 128;
    const int col0 = blockIdx.x * 128;

    float acc[2][8][4];
    #pragma unroll
    for (int i = 0; i < 2; i++)
        #pragma unroll
        for (int j = 0; j < 8; j++)
            #pragma unroll
            for (int l = 0; l < 4; l++) acc[i][j][l] = 0.f;

    for (int k0 = 0; k0 < EEMB; k0 += 32) {
        __syncthreads();
        #pragma unroll
        for (int i = 0; i < 4; i++) {
            int f = tid + i * 256;
            int r = f >> 3, c = (f & 7) * 4;
            float4 av = *(const float4*)(A + (size_t)(row0 + r) * EEMB + k0 + c);
            float4 wv = *(const float4*)(W + (size_t)(col0 + r) * EEMB + k0 + c);
            rnd4(av); rnd4(wv);
            *(float4*)&As[r][c] = av;
            *(float4*)&Bs[r][c] = wv;
        }
        __syncthreads();

        #pragma unroll
        for (int kk = 0; kk < 32; kk += 8) {
            uint32_t af[2][4], bf[8][2];
            #pragma unroll
            for (int tm = 0; tm < 2; tm++) {
                int m = wm * 32 + tm * 16;
                af[tm][0] = __float_as_uint(As[m + gid    ][kk + tig    ]);
                af[tm][1] = __float_as_uint(As[m + gid + 8][kk + tig    ]);
                af[tm][2] = __float_as_uint(As[m + gid    ][kk + tig + 4]);
                af[tm][3] = __float_as_uint(As[m + gid + 8][kk + tig + 4]);
            }
            #pragma unroll
            for (int tn = 0; tn < 8; tn++) {
                int n = wn * 64 + tn * 8;
                bf[tn][0] = __float_as_uint(Bs[n + gid][kk + tig    ]);
                bf[tn][1] = __float_as_uint(Bs[n + gid][kk + tig + 4]);
            }
            #pragma unroll
            for (int tm = 0; tm < 2; tm++)
                #pragma unroll
                for (int tn = 0; tn < 8; tn++)
                    mma8(acc[tm][tn], af[tm][0], af[tm][1], af[tm][2], af[tm][3],
                         bf[tn][0], bf[tn][1]);
        }
    }

    // Epilogue scatter
    #pragma unroll
    for (int tm = 0; tm < 2; tm++) {
        #pragma unroll
        for (int tn = 0; tn < 8; tn++) {
            #pragma unroll
            for (int e = 0; e < 4; e++) {
                int m = row0 + wm * 32 + tm * 16 + gid + (e >= 2 ? 8 : 0);
                int n = col0 + wn * 64 + tn * 8 + 2 * tig + (e & 1);
                int b = m >> 11, s = m & (SSEQ - 1);
                int h = n >> 6,  d = n & (DKK - 1);
                float v = acc[tm][tn][e];
                if (mode == 2) v = cosf(v + __ldg(&theta[d])) * 0.125f;
                dst[((size_t)(b * HHEADS + h) * SSEQ + s) * DKK + d] = v;
            }
        }
    }
}

// =====================================================================
// Attention: CTA = (128 queries, 1 head). 256 thr / 8 warps.
// Key tiles of 64. Exact softmax w/o max-subtraction (|score| <= ~4).
// S-GEMM: warp w -> queries [w*16, w*16+16) x 64 keys.
// PV-GEMM: warp (wm=w>>1, wn=w&1) -> O tile 32q x 32d, accum in regs.
// =====================================================================
#define QS_PAD 68
#define KS_PAD 68
#define VS_PAD 72
#define PS_PAD 68
#define OFF_QS 0
#define OFF_KS (OFF_QS + 128*QS_PAD*4)
#define OFF_VS (OFF_KS + 64*KS_PAD*4)
#define OFF_PS (OFF_VS + 64*VS_PAD*4)
#define OFF_LS (OFF_PS + 128*PS_PAD*4)
#define AT_SMEM (OFF_LS + 128*4)

__global__ __launch_bounds__(256)
void attn_mma(float* __restrict__ out)
{
    extern __shared__ char smem[];
    float (*Qs)[QS_PAD] = (float(*)[QS_PAD])(smem + OFF_QS);
    float (*Ks)[KS_PAD] = (float(*)[KS_PAD])(smem + OFF_KS);
    float (*Vs)[VS_PAD] = (float(*)[VS_PAD])(smem + OFF_VS);
    float (*Ps)[PS_PAD] = (float(*)[PS_PAD])(smem + OFF_PS);
    float* Ls = (float*)(smem + OFF_LS);

    const int tid = threadIdx.x;
    const int wid = tid >> 5, lane = tid & 31;
    const int gid = lane >> 2, tig = lane & 3;
    const int wm = wid >> 1, wn = wid & 1;
    const int bh = blockIdx.y;
    const int s0 = blockIdx.x * 128;
    const int qw = wid * 16;   // S-GEMM query base for this warp

    // Load Q tile [128 x 64] (tf32-rounded)
    {
        const float* qsrc = g_q + ((size_t)bh * SSEQ + s0) * DKK;
        #pragma unroll
        for (int i = 0; i < 8; i++) {
            int f = tid + i * 256;
            int r = f >> 4, c = (f & 15) * 4;
            float4 v = *(const float4*)(qsrc + (size_t)r * DKK + c);
            rnd4(v);
            *(float4*)&Qs[r][c] = v;
        }
    }

    float oacc[2][4][4];
    #pragma unroll
    for (int i = 0; i < 2; i++)
        #pragma unroll
        for (int j = 0; j < 4; j++)
            #pragma unroll
            for (int l = 0; l < 4; l++) oacc[i][j][l] = 0.f;
    float lsum0 = 0.f, lsum1 = 0.f;

    const float* kbase = g_k + (size_t)bh * SSEQ * DKK;
    const float* vbase = g_v + (size_t)bh * SSEQ * DKK;

    #pragma unroll 1
    for (int t = 0; t < SSEQ / 64; t++) {
        const int t0 = t * 64;
        __syncthreads();   // prior S-reads of Ks and PV-reads of Vs done
        #pragma unroll
        for (int i = 0; i < 4; i++) {
            int f = tid + i * 256;
            int r = f >> 4, c = (f & 15) * 4;
            float4 kv = *(const float4*)(kbase + (size_t)(t0 + r) * DKK + c);
            float4 vv = *(const float4*)(vbase + (size_t)(t0 + r) * DKK + c);
            rnd4(kv); rnd4(vv);
            *(float4*)&Ks[r][c] = kv;
            *(float4*)&Vs[r][c] = vv;
        }
        __syncthreads();

        // ---- S = Q @ K^T : 16 q x 64 keys per warp ----
        float sacc[8][4];
        #pragma unroll
        for (int j = 0; j < 8; j++)
            #pragma unroll
            for (int l = 0; l < 4; l++) sacc[j][l] = 0.f;

        #pragma unroll
        for (int kk = 0; kk < 64; kk += 8) {
            uint32_t a0 = __float_as_uint(Qs[qw + gid    ][kk + tig    ]);
            uint32_t a1 = __float_as_uint(Qs[qw + gid + 8][kk + tig    ]);
            uint32_t a2 = __float_as_uint(Qs[qw + gid    ][kk + tig + 4]);
            uint32_t a3 = __float_as_uint(Qs[qw + gid + 8][kk + tig + 4]);
            #pragma unroll
            for (int tn = 0; tn < 8; tn++) {
                uint32_t b0 = __float_as_uint(Ks[tn * 8 + gid][kk + tig    ]);
                uint32_t b1 = __float_as_uint(Ks[tn * 8 + gid][kk + tig + 4]);
                mma8(sacc[tn], a0, a1, a2, a3, b0, b1);
            }
        }

        // ---- exp + row sums + stage P (tf32) ----
        #pragma unroll
        for (int tn = 0; tn < 8; tn++) {
            float p0 = __expf(sacc[tn][0]);
            float p1 = __expf(sacc[tn][1]);
            float p2 = __expf(sacc[tn][2]);
            float p3 = __expf(sacc[tn][3]);
            p0 = to_tf32(p0); p1 = to_tf32(p1);
            p2 = to_tf32(p2); p3 = to_tf32(p3);
            lsum0 += p0 + p1;
            lsum1 += p2 + p3;
            int key = tn * 8 + 2 * tig;
            Ps[qw + gid    ][key    ] = p0;
            Ps[qw + gid    ][key + 1] = p1;
            Ps[qw + gid + 8][key    ] = p2;
            Ps[qw + gid + 8][key + 1] = p3;
        }
        __syncthreads();

        // ---- O += P @ V : warp tile 32q x 32d ----
        #pragma unroll
        for (int kk = 0; kk < 64; kk += 8) {
            uint32_t af[2][4], bf[4][2];
            #pragma unroll
            for (int tm = 0; tm < 2; tm++) {
                int m = wm * 32 + tm * 16;
                af[tm][0] = __float_as_uint(Ps[m + gid    ][kk + tig    ]);
                af[tm][1] = __float_as_uint(Ps[m + gid + 8][kk + tig    ]);
                af[tm][2] = __float_as_uint(Ps[m + gid    ][kk + tig + 4]);
                af[tm][3] = __float_as_uint(Ps[m + gid + 8][kk + tig + 4]);
            }
            #pragma unroll
            for (int tn = 0; tn < 4; tn++) {
                int d = wn * 32 + tn * 8 + gid;
                bf[tn][0] = __float_as_uint(Vs[kk + tig    ][d]);
                bf[tn][1] = __float_as_uint(Vs[kk + tig + 4][d]);
            }
            #pragma unroll
            for (int tm = 0; tm < 2; tm++)
                #pragma unroll
                for (int tn = 0; tn < 4; tn++)
                    mma8(oacc[tm][tn], af[tm][0], af[tm][1], af[tm][2], af[tm][3],
                         bf[tn][0], bf[tn][1]);
        }
    }

    // ---- finalize l (reduce across quad), publish to smem ----
    lsum0 += __shfl_xor_sync(0xFFFFFFFF, lsum0, 1);
    lsum0 += __shfl_xor_sync(0xFFFFFFFF, lsum0, 2);
    lsum1 += __shfl_xor_sync(0xFFFFFFFF, lsum1, 1);
    lsum1 += __shfl_xor_sync(0xFFFFFFFF, lsum1, 2);
    if (tig == 0) {
        Ls[qw + gid]     = lsum0;
        Ls[qw + gid + 8] = lsum1;
    }
    __syncthreads();

    // ---- epilogue: out[b, s0+q, h*64+d] = O / l ----
    const int b = bh >> 4, h = bh & (HHEADS - 1);
    #pragma unroll
    for (int tm = 0; tm < 2; tm++) {
        int r0 = wm * 32 + tm * 16 + gid;
        float inv0 = 1.f / Ls[r0];
        float inv1 = 1.f / Ls[r0 + 8];
        float* o0 = out + ((size_t)b * SSEQ + s0 + r0) * EEMB + h * DKK;
        float* o1 = o0 + 8 * EEMB;
        #pragma unroll
        for (int tn = 0; tn < 4; tn++) {
            int c = wn * 32 + tn * 8 + 2 * tig;
            float2 v0 = make_float2(oacc[tm][tn][0] * inv0, oacc[tm][tn][1] * inv0);
            float2 v1 = make_float2(oacc[tm][tn][2] * inv1, oacc[tm][tn][3] * inv1);
            *(float2*)(o0 + c) = v0;
            *(float2*)(o1 + c) = v1;
        }
    }
}

// ===================== launch =====================
extern "C" void kernel_launch(void* const* d_in, const int* in_sizes, int n_in,
                              void* d_out, int out_size)
{
    const float* x     = (const float*)d_in[0];
    const float* Wk    = (const float*)d_in[1];
    const float* Wv    = (const float*)d_in[2];
    const float* Wq    = (const float*)d_in[3];
    const float* theta = (const float*)d_in[4];
    float* out = (float*)d_out;

    float *gk, *gv, *gq;
    cudaGetSymbolAddress((void**)&gk, g_k);
    cudaGetSymbolAddress((void**)&gv, g_v);
    cudaGetSymbolAddress((void**)&gq, g_q);

    cudaFuncSetAttribute(attn_mma, cudaFuncAttributeMaxDynamicSharedMemorySize, AT_SMEM);

    dim3 gp(EEMB / 128, (BBATCH * SSEQ) / 128);   // (8, 32)
    proj_mma<<<gp, 256>>>(x, Wk, theta, gk, 0);
    proj_mma<<<gp, 256>>>(x, Wv, theta, gv, 1);
    proj_mma<<<gp, 256>>>(x, Wq, theta, gq, 2);

    dim3 ga(SSEQ / 128, BBATCH * HHEADS);          // (16, 32)
    attn_mma<<<ga, 256, AT_SMEM>>>(out);
}